// round 7
// baseline (speedup 1.0000x reference)
#include <cuda_runtime.h>

#define NT 5
#define A_FIX 128
#define MAXA 132   // up to 128 atoms of one type + pad to multiple of 4

__device__ __forceinline__ float fast_sqrt(float x) {
    float r; asm("sqrt.approx.f32 %0, %1;" : "=f"(r) : "f"(x)); return r;
}
__device__ __forceinline__ float fast_ex2(float x) {
    float r; asm("ex2.approx.f32 %0, %1;" : "=f"(r) : "f"(x)); return r;
}
__device__ __forceinline__ float fast_rcp(float x) {
    float r; asm("rcp.approx.f32 %0, %1;" : "=f"(r) : "f"(x)); return r;
}
__device__ __forceinline__ float fast_rsq(float x) {
    float r; asm("rsqrt.approx.f32 %0, %1;" : "=f"(r) : "f"(x)); return r;
}

// one (point,atom) pair, dot-product form
#define PAIR(c, SW, SX, SY, SZ)                                                \
    {                                                                          \
        float dot2 = fmaf((c).x, q2x, fmaf((c).y, q2y, fmaf((c).z, q2z, nqq)));\
        float d2   = (c).w - dot2;             /* |c-q|^2, may be -eps */      \
        float e    = fast_ex2(-fast_sqrt(fabsf(d2)));                          \
        SW += e;                                                               \
        SX = fmaf(e, (c).x, SX);                                               \
        SY = fmaf(e, (c).y, SY);                                               \
        SZ = fmaf(e, (c).z, SZ);                                               \
    }

__global__ __launch_bounds__(256, 4) void gnf_kernel(
    const float* __restrict__ coords,    // [B, A, 3]
    const int*   __restrict__ atom_types,// [B, A]
    const float* __restrict__ query,     // [B, P, 3]
    float*       __restrict__ out,       // [B, P, NT, 3]
    int P)
{
    // atoms of THIS block's type: (L*x, L*y, L*z, |L*c|^2), padded to mult of 4
    __shared__ float4 sc[MAXA];
    __shared__ int cnt;

    const int b   = blockIdx.y;
    const int ty  = blockIdx.z;          // atom type handled by this block
    const int tid = threadIdx.x;
    const float L = 1.4426950408889634f; // log2(e)

    if (tid == 0) cnt = 0;
    if (tid < MAXA) sc[tid] = make_float4(0.0f, 0.0f, 0.0f, 1e30f); // sentinel: e==0
    __syncthreads();

    if (tid < A_FIX && atom_types[b * A_FIX + tid] == ty) {
        int r = atomicAdd(&cnt, 1);
        const float* c = coords + (b * A_FIX + tid) * 3;
        float x = c[0] * L, y = c[1] * L, z = c[2] * L;
        sc[r] = make_float4(x, y, z, fmaf(x, x, fmaf(y, y, z * z)));
    }
    __syncthreads();

    const int n  = cnt;
    const int pe = (n + 3) & ~3;         // padded count, multiple of 4

    const int p = blockIdx.x * blockDim.x + tid;
    if (p >= P) return;

    const float* q = query + ((long)b * P + p) * 3;
    const float qx = q[0] * L, qy = q[1] * L, qz = q[2] * L;
    const float q2x = 2.0f * qx, q2y = 2.0f * qy, q2z = 2.0f * qz;
    const float nqq = -fmaf(qx, qx, fmaf(qy, qy, qz * qz));   // -|qL|^2

    // 2 independent accumulator banks (TLP now carries the latency hiding)
    float w0 = 0.f, x0 = 0.f, y0 = 0.f, z0 = 0.f;
    float w1 = 0.f, x1 = 0.f, y1 = 0.f, z1 = 0.f;

    for (int a = 0; a < pe; a += 4) {
        float4 c0 = sc[a + 0];
        float4 c1 = sc[a + 1];
        float4 c2 = sc[a + 2];
        float4 c3 = sc[a + 3];
        PAIR(c0, w0, x0, y0, z0);
        PAIR(c1, w1, x1, y1, z1);
        PAIR(c2, w0, x0, y0, z0);
        PAIR(c3, w1, x1, y1, z1);
    }

    float sw  = w0 + w1;
    float sxc = x0 + x1;
    float syc = y0 + y1;
    float szc = z0 + z1;

    float gx = 0.0f, gy = 0.0f, gz = 0.0f;
    if (n > 0) {
        const float INVL = 0.6931471805599453f;   // ln(2)
        float inv = fast_rcp(sw) * INVL;          // un-scale by L
        gx = (sxc - qx * sw) * inv;               // sum e*(cx-qx) / sum e
        gy = (syc - qy * sw) * inv;
        gz = (szc - qz * sw) * inv;
        float g2 = fmaf(gx, gx, fmaf(gy, gy, gz * gz));
        float f = fminf(1.0f, 0.3f * fast_rsq(fmaxf(g2, 1e-24f)));
        gx *= f; gy *= f; gz *= f;
    }

    float* o = out + (((long)b * P + p) * NT + ty) * 3;
    o[0] = gx;
    o[1] = gy;
    o[2] = gz;
}

extern "C" void kernel_launch(void* const* d_in, const int* in_sizes, int n_in,
                              void* d_out, int out_size)
{
    const float* coords     = (const float*)d_in[0];  // B*A*3
    const int*   atom_types = (const int*)  d_in[1];  // B*A
    const float* query      = (const float*)d_in[2];  // B*P*3

    const int A = A_FIX;
    const int B = in_sizes[1] / A;
    const int P = in_sizes[2] / (3 * B);

    dim3 grid((P + 255) / 256, B, NT);
    gnf_kernel<<<grid, 256>>>(coords, atom_types, query, (float*)d_out, P);
}

// round 9
// speedup vs baseline: 1.0133x; 1.0133x over previous
#include <cuda_runtime.h>

#define NT 5
#define A_FIX 128
#define MAXA 130          // 128 atoms of one type + pad to multiple of 2
#define THREADS 256
#define PPT 2             // points per thread
#define PTS_PER_BLK (THREADS * PPT)   // 512

typedef unsigned long long ull;

__device__ __forceinline__ float fast_sqrt(float x) {
    float r; asm("sqrt.approx.f32 %0, %1;" : "=f"(r) : "f"(x)); return r;
}
__device__ __forceinline__ float fast_ex2(float x) {
    float r; asm("ex2.approx.f32 %0, %1;" : "=f"(r) : "f"(x)); return r;
}
__device__ __forceinline__ float fast_rcp(float x) {
    float r; asm("rcp.approx.f32 %0, %1;" : "=f"(r) : "f"(x)); return r;
}
__device__ __forceinline__ float fast_rsq(float x) {
    float r; asm("rsqrt.approx.f32 %0, %1;" : "=f"(r) : "f"(x)); return r;
}

// ---- packed f32x2 helpers (Blackwell; mirrors ptx_helpers.cuh macros) ----
__device__ __forceinline__ ull pack2(float lo, float hi) {
    ull r;
    asm("mov.b64 %0, {%1, %2};" : "=l"(r) : "r"(__float_as_uint(lo)), "r"(__float_as_uint(hi)));
    return r;
}
__device__ __forceinline__ void unpack2(ull v, float& lo, float& hi) {
    unsigned int a, b;
    asm("mov.b64 {%0, %1}, %2;" : "=r"(a), "=r"(b) : "l"(v));
    lo = __uint_as_float(a); hi = __uint_as_float(b);
}
__device__ __forceinline__ ull ffma2(ull a, ull b, ull c) {
    ull d; asm("fma.rn.f32x2 %0, %1, %2, %3;" : "=l"(d) : "l"(a), "l"(b), "l"(c)); return d;
}
__device__ __forceinline__ ull fadd2(ull a, ull b) {
    ull d; asm("add.rn.f32x2 %0, %1, %2;" : "=l"(d) : "l"(a), "l"(b)); return d;
}

// one atom vs the 2 packed points; accumulates into one bank
#define PAIR2(ca, cb, SW, SX, SY, SZ)                                          \
    {                                                                          \
        ull dot = ffma2((ca).x, nq2x, ffma2((ca).y, nq2y,                      \
                     ffma2((cb).x, nq2z, nqq2)));   /* -2c.q + |q|^2 */        \
        ull d2p = fadd2((cb).y, dot);               /* |c-q|^2 both points */  \
        float d0, d1; unpack2(d2p, d0, d1);                                    \
        float e0 = fast_ex2(-fast_sqrt(fabsf(d0)));                            \
        float e1 = fast_ex2(-fast_sqrt(fabsf(d1)));                            \
        ull e2 = pack2(e0, e1);                                                \
        SW = fadd2(SW, e2);                                                    \
        SX = ffma2(e2, (ca).x, SX);                                            \
        SY = ffma2(e2, (ca).y, SY);                                            \
        SZ = ffma2(e2, (cb).x, SZ);                                            \
    }

__global__ __launch_bounds__(THREADS) void gnf_kernel(
    const float* __restrict__ coords,    // [B, A, 3]
    const int*   __restrict__ atom_types,// [B, A]
    const float* __restrict__ query,     // [B, P, 3]
    float*       __restrict__ out,       // [B, P, NT, 3]
    int P)
{
    // atoms of THIS block's type, each value duplicated into both f32x2 lanes:
    // sA[a] = (x2, y2), sB[a] = (z2, w2) where w = |L*c|^2
    __shared__ ulonglong2 sA[MAXA];
    __shared__ ulonglong2 sB[MAXA];
    __shared__ int cnt;

    const int b   = blockIdx.y;
    const int ty  = blockIdx.z;
    const int tid = threadIdx.x;
    const float L = 1.4426950408889634f;   // log2(e)

    if (tid == 0) cnt = 0;
    if (tid < MAXA) {
        sA[tid] = make_ulonglong2(0ull, 0ull);
        sB[tid] = make_ulonglong2(0ull, pack2(1e30f, 1e30f));  // sentinel: e == 0
    }
    __syncthreads();

    if (tid < A_FIX && atom_types[b * A_FIX + tid] == ty) {
        int r = atomicAdd(&cnt, 1);
        const float* c = coords + (b * A_FIX + tid) * 3;
        float x = c[0] * L, y = c[1] * L, z = c[2] * L;
        float w = fmaf(x, x, fmaf(y, y, z * z));
        sA[r] = make_ulonglong2(pack2(x, x), pack2(y, y));
        sB[r] = make_ulonglong2(pack2(z, z), pack2(w, w));
    }
    __syncthreads();

    const int n  = cnt;
    const int pe = (n + 1) & ~1;           // padded to multiple of 2

    const int p0 = blockIdx.x * PTS_PER_BLK + tid;
    const int p1 = p0 + THREADS;
    const int cp0 = (p0 < P) ? p0 : (P - 1);
    const int cp1 = (p1 < P) ? p1 : (P - 1);

    const float* q0 = query + ((long)b * P + cp0) * 3;
    const float* q1 = query + ((long)b * P + cp1) * 3;
    const float q0x = q0[0] * L, q0y = q0[1] * L, q0z = q0[2] * L;
    const float q1x = q1[0] * L, q1y = q1[1] * L, q1z = q1[2] * L;
    const float qq0 = fmaf(q0x, q0x, fmaf(q0y, q0y, q0z * q0z));  // +|qL|^2
    const float qq1 = fmaf(q1x, q1x, fmaf(q1y, q1y, q1z * q1z));

    const ull nq2x = pack2(-2.0f * q0x, -2.0f * q1x);
    const ull nq2y = pack2(-2.0f * q0y, -2.0f * q1y);
    const ull nq2z = pack2(-2.0f * q0z, -2.0f * q1z);
    const ull nqq2 = pack2(qq0, qq1);

    // 2 accumulator banks (atoms alternate) -> 4 independent MUFU chains
    ull wA = 0, xA = 0, yA = 0, zA = 0;
    ull wB = 0, xB = 0, yB = 0, zB = 0;

    for (int a = 0; a < pe; a += 2) {
        ulonglong2 a0 = sA[a],     b0 = sB[a];
        ulonglong2 a1 = sA[a + 1], b1 = sB[a + 1];
        PAIR2(a0, b0, wA, xA, yA, zA);
        PAIR2(a1, b1, wB, xB, yB, zB);
    }

    ull sw2 = fadd2(wA, wB);
    ull sx2 = fadd2(xA, xB);
    ull sy2 = fadd2(yA, yB);
    ull sz2 = fadd2(zA, zB);

    float sw0, sw1, sx0, sx1, sy0, sy1, sz0, sz1;
    unpack2(sw2, sw0, sw1);
    unpack2(sx2, sx0, sx1);
    unpack2(sy2, sy0, sy1);
    unpack2(sz2, sz0, sz1);

    const float INVL = 0.6931471805599453f;  // ln(2)

    if (p0 < P) {
        float gx = 0.f, gy = 0.f, gz = 0.f;
        if (n > 0) {
            float inv = fast_rcp(sw0) * INVL;
            gx = (sx0 - q0x * sw0) * inv;
            gy = (sy0 - q0y * sw0) * inv;
            gz = (sz0 - q0z * sw0) * inv;
            float g2 = fmaf(gx, gx, fmaf(gy, gy, gz * gz));
            float f = fminf(1.0f, 0.3f * fast_rsq(fmaxf(g2, 1e-24f)));
            gx *= f; gy *= f; gz *= f;
        }
        float* o = out + (((long)b * P + p0) * NT + ty) * 3;
        o[0] = gx; o[1] = gy; o[2] = gz;
    }
    if (p1 < P) {
        float gx = 0.f, gy = 0.f, gz = 0.f;
        if (n > 0) {
            float inv = fast_rcp(sw1) * INVL;
            gx = (sx1 - q1x * sw1) * inv;
            gy = (sy1 - q1y * sw1) * inv;
            gz = (sz1 - q1z * sw1) * inv;
            float g2 = fmaf(gx, gx, fmaf(gy, gy, gz * gz));
            float f = fminf(1.0f, 0.3f * fast_rsq(fmaxf(g2, 1e-24f)));
            gx *= f; gy *= f; gz *= f;
        }
        float* o = out + (((long)b * P + p1) * NT + ty) * 3;
        o[0] = gx; o[1] = gy; o[2] = gz;
    }
}

extern "C" void kernel_launch(void* const* d_in, const int* in_sizes, int n_in,
                              void* d_out, int out_size)
{
    const float* coords     = (const float*)d_in[0];  // B*A*3
    const int*   atom_types = (const int*)  d_in[1];  // B*A
    const float* query      = (const float*)d_in[2];  // B*P*3

    const int A = A_FIX;
    const int B = in_sizes[1] / A;
    const int P = in_sizes[2] / (3 * B);

    dim3 grid((P + PTS_PER_BLK - 1) / PTS_PER_BLK, B, NT);
    gnf_kernel<<<grid, THREADS>>>(coords, atom_types, query, (float*)d_out, P);
}

// round 10
// speedup vs baseline: 1.0179x; 1.0045x over previous
#include <cuda_runtime.h>

#define NT 5
#define A_FIX 128
#define MAXP 66          // max atom-pairs of one type (128/2 + padding)
#define THREADS 256

typedef unsigned long long ull;

__device__ __forceinline__ float fast_sqrt(float x) {
    float r; asm("sqrt.approx.f32 %0, %1;" : "=f"(r) : "f"(x)); return r;
}
__device__ __forceinline__ float fast_ex2(float x) {
    float r; asm("ex2.approx.f32 %0, %1;" : "=f"(r) : "f"(x)); return r;
}
__device__ __forceinline__ float fast_rcp(float x) {
    float r; asm("rcp.approx.f32 %0, %1;" : "=f"(r) : "f"(x)); return r;
}
__device__ __forceinline__ float fast_rsq(float x) {
    float r; asm("rsqrt.approx.f32 %0, %1;" : "=f"(r) : "f"(x)); return r;
}

__device__ __forceinline__ ull pack2(float lo, float hi) {
    ull r;
    asm("mov.b64 %0, {%1, %2};" : "=l"(r) : "r"(__float_as_uint(lo)), "r"(__float_as_uint(hi)));
    return r;
}
__device__ __forceinline__ void unpack2(ull v, float& lo, float& hi) {
    unsigned int a, b;
    asm("mov.b64 {%0, %1}, %2;" : "=r"(a), "=r"(b) : "l"(v));
    lo = __uint_as_float(a); hi = __uint_as_float(b);
}
__device__ __forceinline__ ull ffma2(ull a, ull b, ull c) {
    ull d; asm("fma.rn.f32x2 %0, %1, %2, %3;" : "=l"(d) : "l"(a), "l"(b), "l"(c)); return d;
}
__device__ __forceinline__ ull fadd2(ull a, ull b) {
    ull d; asm("add.rn.f32x2 %0, %1, %2;" : "=l"(d) : "l"(a), "l"(b)); return d;
}

// one atom-PAIR vs this thread's point; accumulates into one bank
// xy = (x_a,x_b | y_a,y_b), zw = (z_a,z_b | w_a,w_b), w = |L*c|^2
#define PAIRA(xy, zw, SW, SX, SY, SZ)                                          \
    {                                                                          \
        ull dot = ffma2((xy).x, nq2x, ffma2((xy).y, nq2y,                      \
                     ffma2((zw).x, nq2z, nqq2)));   /* -2c.q + |q|^2 */        \
        ull d2p = fadd2((zw).y, dot);               /* |c-q|^2 both atoms */   \
        float d0, d1; unpack2(d2p, d0, d1);                                    \
        float e0 = fast_ex2(-fast_sqrt(fabsf(d0)));                            \
        float e1 = fast_ex2(-fast_sqrt(fabsf(d1)));                            \
        ull e2 = pack2(e0, e1);                                                \
        SW = fadd2(SW, e2);                                                    \
        SX = ffma2(e2, (xy).x, SX);                                            \
        SY = ffma2(e2, (xy).y, SY);                                            \
        SZ = ffma2(e2, (zw).x, SZ);                                            \
    }

__global__ __launch_bounds__(THREADS, 4) void gnf_kernel(
    const float* __restrict__ coords,    // [B, A, 3]
    const int*   __restrict__ atom_types,// [B, A]
    const float* __restrict__ query,     // [B, P, 3]
    float*       __restrict__ out,       // [B, P, NT, 3]
    int P)
{
    // atom-pair SoA: sXY[j] = (x_a,x_b,y_a,y_b), sZW[j] = (z_a,z_b,w_a,w_b)
    __shared__ __align__(16) float sXY[MAXP * 4];
    __shared__ __align__(16) float sZW[MAXP * 4];
    __shared__ int cnt;

    const int b   = blockIdx.y;
    const int ty  = blockIdx.z;
    const int tid = threadIdx.x;
    const float L = 1.4426950408889634f;   // log2(e)

    if (tid == 0) cnt = 0;
    // sentinel fill: w = 1e30 -> e == 0 exactly; x=y=z=0
    for (int i = tid; i < MAXP * 4; i += THREADS) {
        sXY[i] = 0.0f;
        sZW[i] = ((i & 3) >= 2) ? 1e30f : 0.0f;
    }
    __syncthreads();

    if (tid < A_FIX && atom_types[b * A_FIX + tid] == ty) {
        int r = atomicAdd(&cnt, 1);
        const float* c = coords + (b * A_FIX + tid) * 3;
        float x = c[0] * L, y = c[1] * L, z = c[2] * L;
        float w = fmaf(x, x, fmaf(y, y, z * z));
        int j = r >> 1, h = r & 1;
        sXY[4 * j + h]     = x;
        sXY[4 * j + 2 + h] = y;
        sZW[4 * j + h]     = z;
        sZW[4 * j + 2 + h] = w;
    }
    __syncthreads();

    const int n   = cnt;
    const int npj = (n + 3) >> 2 << 1;     // atom-pairs, padded to multiple of 2

    const int p = blockIdx.x * THREADS + tid;
    if (p >= P) return;

    const float* q = query + ((long)b * P + p) * 3;
    const float qx = q[0] * L, qy = q[1] * L, qz = q[2] * L;
    const float qq = fmaf(qx, qx, fmaf(qy, qy, qz * qz));   // +|qL|^2

    const ull nq2x = pack2(-2.0f * qx, -2.0f * qx);
    const ull nq2y = pack2(-2.0f * qy, -2.0f * qy);
    const ull nq2z = pack2(-2.0f * qz, -2.0f * qz);
    const ull nqq2 = pack2(qq, qq);

    const ulonglong2* pXY = (const ulonglong2*)sXY;
    const ulonglong2* pZW = (const ulonglong2*)sZW;

    // 2 banks -> 4 independent MUFU chains
    ull wA = 0, xA = 0, yA = 0, zA = 0;
    ull wB = 0, xB = 0, yB = 0, zB = 0;

    for (int j = 0; j < npj; j += 2) {
        ulonglong2 xy0 = pXY[j],     zw0 = pZW[j];
        ulonglong2 xy1 = pXY[j + 1], zw1 = pZW[j + 1];
        PAIRA(xy0, zw0, wA, xA, yA, zA);
        PAIRA(xy1, zw1, wB, xB, yB, zB);
    }

    ull sw2 = fadd2(wA, wB);
    ull sx2 = fadd2(xA, xB);
    ull sy2 = fadd2(yA, yB);
    ull sz2 = fadd2(zA, zB);

    float swl, swh, sxl, sxh, syl, syh, szl, szh;
    unpack2(sw2, swl, swh);
    unpack2(sx2, sxl, sxh);
    unpack2(sy2, syl, syh);
    unpack2(sz2, szl, szh);
    float sw = swl + swh, sxc = sxl + sxh, syc = syl + syh, szc = szl + szh;

    float gx = 0.f, gy = 0.f, gz = 0.f;
    if (n > 0) {
        const float INVL = 0.6931471805599453f;   // ln(2)
        float inv = fast_rcp(sw) * INVL;          // un-scale by L
        gx = (sxc - qx * sw) * inv;               // sum e*(cx-qx) / sum e
        gy = (syc - qy * sw) * inv;
        gz = (szc - qz * sw) * inv;
        float g2 = fmaf(gx, gx, fmaf(gy, gy, gz * gz));
        float f = fminf(1.0f, 0.3f * fast_rsq(fmaxf(g2, 1e-24f)));
        gx *= f; gy *= f; gz *= f;
    }

    float* o = out + (((long)b * P + p) * NT + ty) * 3;
    o[0] = gx; o[1] = gy; o[2] = gz;
}

extern "C" void kernel_launch(void* const* d_in, const int* in_sizes, int n_in,
                              void* d_out, int out_size)
{
    const float* coords     = (const float*)d_in[0];  // B*A*3
    const int*   atom_types = (const int*)  d_in[1];  // B*A
    const float* query      = (const float*)d_in[2];  // B*P*3

    const int A = A_FIX;
    const int B = in_sizes[1] / A;
    const int P = in_sizes[2] / (3 * B);

    dim3 grid((P + THREADS - 1) / THREADS, B, NT);
    gnf_kernel<<<grid, THREADS>>>(coords, atom_types, query, (float*)d_out, P);
}

// round 11
// speedup vs baseline: 1.0201x; 1.0022x over previous
#include <cuda_runtime.h>

#define NT 5
#define A_FIX 128
#define MAXP 66          // max atom-pairs of one type (128/2 + padding)
#define THREADS 256

typedef unsigned long long ull;

__device__ __forceinline__ float fast_sqrt(float x) {
    float r; asm("sqrt.approx.f32 %0, %1;" : "=f"(r) : "f"(x)); return r;
}
__device__ __forceinline__ float fast_ex2(float x) {
    float r; asm("ex2.approx.f32 %0, %1;" : "=f"(r) : "f"(x)); return r;
}
__device__ __forceinline__ float fast_rcp(float x) {
    float r; asm("rcp.approx.f32 %0, %1;" : "=f"(r) : "f"(x)); return r;
}
__device__ __forceinline__ float fast_rsq(float x) {
    float r; asm("rsqrt.approx.f32 %0, %1;" : "=f"(r) : "f"(x)); return r;
}

__device__ __forceinline__ ull pack2(float lo, float hi) {
    ull r;
    asm("mov.b64 %0, {%1, %2};" : "=l"(r) : "r"(__float_as_uint(lo)), "r"(__float_as_uint(hi)));
    return r;
}
__device__ __forceinline__ void unpack2(ull v, float& lo, float& hi) {
    unsigned int a, b;
    asm("mov.b64 {%0, %1}, %2;" : "=r"(a), "=r"(b) : "l"(v));
    lo = __uint_as_float(a); hi = __uint_as_float(b);
}
__device__ __forceinline__ ull ffma2(ull a, ull b, ull c) {
    ull d; asm("fma.rn.f32x2 %0, %1, %2, %3;" : "=l"(d) : "l"(a), "l"(b), "l"(c)); return d;
}
__device__ __forceinline__ ull fadd2(ull a, ull b) {
    ull d; asm("add.rn.f32x2 %0, %1, %2;" : "=l"(d) : "l"(a), "l"(b)); return d;
}

// one atom-PAIR vs this thread's point; accumulates into one bank
// xy = (x_a,x_b | y_a,y_b), zw = (z_a,z_b | w_a,w_b), w = |L*c|^2
#define PAIRA(xy, zw, SW, SX, SY, SZ)                                          \
    {                                                                          \
        ull dot = ffma2((xy).x, nq2x, ffma2((xy).y, nq2y,                      \
                     ffma2((zw).x, nq2z, nqq2)));   /* -2c.q + |q|^2 */        \
        ull d2p = fadd2((zw).y, dot);               /* |c-q|^2 both atoms */   \
        float d0, d1; unpack2(d2p, d0, d1);                                    \
        float e0 = fast_ex2(-fast_sqrt(fabsf(d0)));                            \
        float e1 = fast_ex2(-fast_sqrt(fabsf(d1)));                            \
        ull e2 = pack2(e0, e1);                                                \
        SW = fadd2(SW, e2);                                                    \
        SX = ffma2(e2, (xy).x, SX);                                            \
        SY = ffma2(e2, (xy).y, SY);                                            \
        SZ = ffma2(e2, (zw).x, SZ);                                            \
    }

__global__ __launch_bounds__(THREADS, 5) void gnf_kernel(
    const float* __restrict__ coords,    // [B, A, 3]
    const int*   __restrict__ atom_types,// [B, A]
    const float* __restrict__ query,     // [B, P, 3]
    float*       __restrict__ out,       // [B, P, NT, 3]
    int P)
{
    // atom-pair SoA: sXY[j] = (x_a,x_b,y_a,y_b), sZW[j] = (z_a,z_b,w_a,w_b)
    __shared__ __align__(16) float sXY[MAXP * 4];
    __shared__ __align__(16) float sZW[MAXP * 4];
    __shared__ int cnt;

    const int b   = blockIdx.y;
    const int ty  = blockIdx.z;
    const int tid = threadIdx.x;
    const float L = 1.4426950408889634f;   // log2(e)

    if (tid == 0) cnt = 0;
    // sentinel fill: w = 1e30 -> e == 0 exactly; x=y=z=0
    for (int i = tid; i < MAXP * 4; i += THREADS) {
        sXY[i] = 0.0f;
        sZW[i] = ((i & 3) >= 2) ? 1e30f : 0.0f;
    }
    __syncthreads();

    if (tid < A_FIX && atom_types[b * A_FIX + tid] == ty) {
        int r = atomicAdd(&cnt, 1);
        const float* c = coords + (b * A_FIX + tid) * 3;
        float x = c[0] * L, y = c[1] * L, z = c[2] * L;
        float w = fmaf(x, x, fmaf(y, y, z * z));
        int j = r >> 1, h = r & 1;
        sXY[4 * j + h]     = x;
        sXY[4 * j + 2 + h] = y;
        sZW[4 * j + h]     = z;
        sZW[4 * j + 2 + h] = w;
    }
    __syncthreads();

    const int n   = cnt;
    const int npj = (n + 3) >> 2 << 1;     // atom-pairs, padded to multiple of 2

    const int p = blockIdx.x * THREADS + tid;
    if (p >= P) return;

    const float* q = query + ((long)b * P + p) * 3;
    const float qx = q[0] * L, qy = q[1] * L, qz = q[2] * L;
    const float qq = fmaf(qx, qx, fmaf(qy, qy, qz * qz));   // +|qL|^2

    const ull nq2x = pack2(-2.0f * qx, -2.0f * qx);
    const ull nq2y = pack2(-2.0f * qy, -2.0f * qy);
    const ull nq2z = pack2(-2.0f * qz, -2.0f * qz);
    const ull nqq2 = pack2(qq, qq);

    const ulonglong2* pXY = (const ulonglong2*)sXY;
    const ulonglong2* pZW = (const ulonglong2*)sZW;

    // 2 banks -> 4 independent MUFU chains
    ull wA = 0, xA = 0, yA = 0, zA = 0;
    ull wB = 0, xB = 0, yB = 0, zB = 0;

    for (int j = 0; j < npj; j += 2) {
        ulonglong2 xy0 = pXY[j],     zw0 = pZW[j];
        ulonglong2 xy1 = pXY[j + 1], zw1 = pZW[j + 1];
        PAIRA(xy0, zw0, wA, xA, yA, zA);
        PAIRA(xy1, zw1, wB, xB, yB, zB);
    }

    ull sw2 = fadd2(wA, wB);
    ull sx2 = fadd2(xA, xB);
    ull sy2 = fadd2(yA, yB);
    ull sz2 = fadd2(zA, zB);

    float swl, swh, sxl, sxh, syl, syh, szl, szh;
    unpack2(sw2, swl, swh);
    unpack2(sx2, sxl, sxh);
    unpack2(sy2, syl, syh);
    unpack2(sz2, szl, szh);
    float sw = swl + swh, sxc = sxl + sxh, syc = syl + syh, szc = szl + szh;

    float gx = 0.f, gy = 0.f, gz = 0.f;
    if (n > 0) {
        const float INVL = 0.6931471805599453f;   // ln(2)
        float inv = fast_rcp(sw) * INVL;          // un-scale by L
        gx = (sxc - qx * sw) * inv;               // sum e*(cx-qx) / sum e
        gy = (syc - qy * sw) * inv;
        gz = (szc - qz * sw) * inv;
        float g2 = fmaf(gx, gx, fmaf(gy, gy, gz * gz));
        float f = fminf(1.0f, 0.3f * fast_rsq(fmaxf(g2, 1e-24f)));
        gx *= f; gy *= f; gz *= f;
    }

    float* o = out + (((long)b * P + p) * NT + ty) * 3;
    o[0] = gx; o[1] = gy; o[2] = gz;
}

extern "C" void kernel_launch(void* const* d_in, const int* in_sizes, int n_in,
                              void* d_out, int out_size)
{
    const float* coords     = (const float*)d_in[0];  // B*A*3
    const int*   atom_types = (const int*)  d_in[1];  // B*A
    const float* query      = (const float*)d_in[2];  // B*P*3

    const int A = A_FIX;
    const int B = in_sizes[1] / A;
    const int P = in_sizes[2] / (3 * B);

    dim3 grid((P + THREADS - 1) / THREADS, B, NT);
    gnf_kernel<<<grid, THREADS>>>(coords, atom_types, query, (float*)d_out, P);
}

// round 12
// speedup vs baseline: 1.0962x; 1.0745x over previous
#include <cuda_runtime.h>

#define NT 5
#define A_FIX 128
#define MAXP 66          // max atom-pairs of one type (128/2 + padding)
#define THREADS 256

typedef unsigned long long ull;

__device__ __forceinline__ float fast_sqrt(float x) {
    float r; asm("sqrt.approx.f32 %0, %1;" : "=f"(r) : "f"(x)); return r;
}
__device__ __forceinline__ float fast_ex2(float x) {
    float r; asm("ex2.approx.f32 %0, %1;" : "=f"(r) : "f"(x)); return r;
}
__device__ __forceinline__ float fast_rcp(float x) {
    float r; asm("rcp.approx.f32 %0, %1;" : "=f"(r) : "f"(x)); return r;
}
__device__ __forceinline__ float fast_rsq(float x) {
    float r; asm("rsqrt.approx.f32 %0, %1;" : "=f"(r) : "f"(x)); return r;
}

__device__ __forceinline__ ull pack2(float lo, float hi) {
    ull r;
    asm("mov.b64 %0, {%1, %2};" : "=l"(r) : "r"(__float_as_uint(lo)), "r"(__float_as_uint(hi)));
    return r;
}
__device__ __forceinline__ void unpack2(ull v, float& lo, float& hi) {
    unsigned int a, b;
    asm("mov.b64 {%0, %1}, %2;" : "=r"(a), "=r"(b) : "l"(v));
    lo = __uint_as_float(a); hi = __uint_as_float(b);
}
__device__ __forceinline__ ull ffma2(ull a, ull b, ull c) {
    ull d; asm("fma.rn.f32x2 %0, %1, %2, %3;" : "=l"(d) : "l"(a), "l"(b), "l"(c)); return d;
}
__device__ __forceinline__ ull fadd2(ull a, ull b) {
    ull d; asm("add.rn.f32x2 %0, %1, %2;" : "=l"(d) : "l"(a), "l"(b)); return d;
}

// one atom-PAIR vs this thread's point; accumulates into one bank
// xy = (x_a,x_b | y_a,y_b), zw = (z_a,z_b | w_a,w_b), w = |L*c|^2
#define PAIRA(xy, zw, SW, SX, SY, SZ)                                          \
    {                                                                          \
        ull dot = ffma2((xy).x, nq2x, ffma2((xy).y, nq2y,                      \
                     ffma2((zw).x, nq2z, nqq2)));   /* -2c.q + |q|^2 */        \
        ull d2p = fadd2((zw).y, dot);               /* |c-q|^2 both atoms */   \
        float d0, d1; unpack2(d2p, d0, d1);                                    \
        float e0 = fast_ex2(-fast_sqrt(fabsf(d0)));                            \
        float e1 = fast_ex2(-fast_sqrt(fabsf(d1)));                            \
        ull e2 = pack2(e0, e1);                                                \
        SW = fadd2(SW, e2);                                                    \
        SX = ffma2(e2, (xy).x, SX);                                            \
        SY = ffma2(e2, (xy).y, SY);                                            \
        SZ = ffma2(e2, (zw).x, SZ);                                            \
    }

__global__ __launch_bounds__(THREADS, 5) void gnf_kernel(
    const float* __restrict__ coords,    // [B, A, 3]
    const int*   __restrict__ atom_types,// [B, A]
    const float* __restrict__ query,     // [B, P, 3]
    float*       __restrict__ out,       // [B, P, NT, 3]
    int P)
{
    // interleaved atom-pair SoA: sAT[2j] = (xa,xb,ya,yb), sAT[2j+1] = (za,zb,wa,wb)
    __shared__ __align__(16) float sAT[MAXP * 8];
    __shared__ int cnt;

    const int b   = blockIdx.y;
    const int ty  = blockIdx.z;
    const int tid = threadIdx.x;
    const float L = 1.4426950408889634f;   // log2(e)

    // ---- init: counter + sentinel fill (w = 1e30 -> e == 0 exactly) ----
    if (tid == 0) cnt = 0;
    for (int i = tid; i < MAXP * 8; i += THREADS)
        sAT[i] = ((i & 7) >= 6) ? 1e30f : 0.0f;
    __syncthreads();

    // ---- ballot-based bucketing: 1 atomic per warp, popc ranks ----
    {
        const bool mine = (tid < A_FIX) && (atom_types[b * A_FIX + tid] == ty);
        const unsigned mask = __ballot_sync(0xFFFFFFFFu, mine);
        const int lane = tid & 31;
        int base = 0;
        if (mask) {
            if (lane == 0) base = atomicAdd(&cnt, __popc(mask));
            base = __shfl_sync(0xFFFFFFFFu, base, 0);
        }
        if (mine) {
            int r = base + __popc(mask & ((1u << lane) - 1u));
            const float* c = coords + (b * A_FIX + tid) * 3;
            float x = c[0] * L, y = c[1] * L, z = c[2] * L;
            float w = fmaf(x, x, fmaf(y, y, z * z));
            int j = r >> 1, h = r & 1;
            sAT[8 * j + h]     = x;
            sAT[8 * j + 2 + h] = y;
            sAT[8 * j + 4 + h] = z;
            sAT[8 * j + 6 + h] = w;
        }
    }
    __syncthreads();

    const int n   = cnt;
    const int npj = (n + 3) >> 2 << 1;     // atom-pairs, padded to multiple of 2

    const int p = blockIdx.x * THREADS + tid;
    if (p >= P) return;

    const float* q = query + ((long)b * P + p) * 3;
    const float qx = q[0] * L, qy = q[1] * L, qz = q[2] * L;
    const float qq = fmaf(qx, qx, fmaf(qy, qy, qz * qz));   // +|qL|^2

    const ull nq2x = pack2(-2.0f * qx, -2.0f * qx);
    const ull nq2y = pack2(-2.0f * qy, -2.0f * qy);
    const ull nq2z = pack2(-2.0f * qz, -2.0f * qz);
    const ull nqq2 = pack2(qq, qq);

    const ulonglong2* pA = (const ulonglong2*)sAT;

    // 2 banks -> 4 independent MUFU chains
    ull wA = 0, xA = 0, yA = 0, zA = 0;
    ull wB = 0, xB = 0, yB = 0, zB = 0;

    for (int k = 0; k < 2 * npj; k += 4) {
        ulonglong2 xy0 = pA[k],     zw0 = pA[k + 1];
        ulonglong2 xy1 = pA[k + 2], zw1 = pA[k + 3];
        PAIRA(xy0, zw0, wA, xA, yA, zA);
        PAIRA(xy1, zw1, wB, xB, yB, zB);
    }

    ull sw2 = fadd2(wA, wB);
    ull sx2 = fadd2(xA, xB);
    ull sy2 = fadd2(yA, yB);
    ull sz2 = fadd2(zA, zB);

    float swl, swh, sxl, sxh, syl, syh, szl, szh;
    unpack2(sw2, swl, swh);
    unpack2(sx2, sxl, sxh);
    unpack2(sy2, syl, syh);
    unpack2(sz2, szl, szh);
    float sw = swl + swh, sxc = sxl + sxh, syc = syl + syh, szc = szl + szh;

    float gx = 0.f, gy = 0.f, gz = 0.f;
    if (n > 0) {
        const float INVL = 0.6931471805599453f;   // ln(2)
        float inv = fast_rcp(sw) * INVL;          // un-scale by L
        gx = (sxc - qx * sw) * inv;               // sum e*(cx-qx) / sum e
        gy = (syc - qy * sw) * inv;
        gz = (szc - qz * sw) * inv;
        float g2 = fmaf(gx, gx, fmaf(gy, gy, gz * gz));
        float f = fminf(1.0f, 0.3f * fast_rsq(fmaxf(g2, 1e-24f)));
        gx *= f; gy *= f; gz *= f;
    }

    float* o = out + (((long)b * P + p) * NT + ty) * 3;
    o[0] = gx; o[1] = gy; o[2] = gz;
}

extern "C" void kernel_launch(void* const* d_in, const int* in_sizes, int n_in,
                              void* d_out, int out_size)
{
    const float* coords     = (const float*)d_in[0];  // B*A*3
    const int*   atom_types = (const int*)  d_in[1];  // B*A
    const float* query      = (const float*)d_in[2];  // B*P*3

    const int A = A_FIX;
    const int B = in_sizes[1] / A;
    const int P = in_sizes[2] / (3 * B);

    dim3 grid((P + THREADS - 1) / THREADS, B, NT);
    gnf_kernel<<<grid, THREADS>>>(coords, atom_types, query, (float*)d_out, P);
}